// round 12
// baseline (speedup 1.0000x reference)
#include <cuda_runtime.h>
#include <cuda_bf16.h>
#include <cstdint>

#define NN       4096
#define NODES    32768
#define DT_STEP  0.25f
#define N_STEPS  18
#define TMN      64                  // nodes (M) per block
#define NBLK     (NODES / TMN)       // 512
#define NTHR     256
#define POFF     32                  // p-field offset within 80-float node record

#define SA       136                 // A1 row stride (elems) = 272 B
#define SM_A1    0                                 // A1: 64 x 136 x 2B = 17408
#define SM_RED   17408                             // reduction: 64 slots x 32 lanes x 16B
#define SM_TOTAL (17408 + 32768)                   // 50176 B -> 4 blocks/SM

// B1 fragments: [net][wn/32][f(0..3 hi,4..7 lo)][half][lane] (ldmatrix x4 regs)
__device__ uint4 g_B1f[2][4][8][2][32];
// B2 fragments: [net][n-group(8 cols)][k-tile(0..7 hi, 8..15 lo)][lane] (ldmatrix x2 regs)
__device__ uint2 g_B2f[2][4][16][32];
// xi A-side fragments per 32-node group: [g][hi/lo][mi][lane]
__device__ uint4 g_XIf[NODES / 32][2][2][32];
// xi/bias B-side fragments: [net][wn/32][f: 0=WXhi 1=WXlo 2=bias][half][lane]
__device__ uint4 g_BXf[2][4][3][2][32];

// ---------------------------------------------------------------------------
__device__ __forceinline__ uint32_t smem_u32(const void* p) {
    uint32_t a;
    asm("{ .reg .u64 t; cvta.to.shared.u64 t, %1; cvt.u32.u64 %0, t; }" : "=r"(a) : "l"(p));
    return a;
}
__device__ __forceinline__ void ldsm_x4(uint32_t (&r)[4], uint32_t addr) {
    asm volatile("ldmatrix.sync.aligned.m8n8.x4.shared.b16 {%0,%1,%2,%3}, [%4];"
        : "=r"(r[0]), "=r"(r[1]), "=r"(r[2]), "=r"(r[3]) : "r"(addr));
}
__device__ __forceinline__ void ldsm_x2(uint32_t (&r)[2], uint32_t addr) {
    asm volatile("ldmatrix.sync.aligned.m8n8.x2.shared.b16 {%0,%1}, [%2];"
        : "=r"(r[0]), "=r"(r[1]) : "r"(addr));
}
__device__ __forceinline__ void mma16816(float (&c)[4], const uint32_t (&a)[4],
                                         uint32_t b0, uint32_t b1) {
    asm volatile("mma.sync.aligned.m16n8k16.row.col.f32.bf16.bf16.f32 "
        "{%0,%1,%2,%3}, {%4,%5,%6,%7}, {%8,%9}, {%0,%1,%2,%3};"
        : "+f"(c[0]), "+f"(c[1]), "+f"(c[2]), "+f"(c[3])
        : "r"(a[0]), "r"(a[1]), "r"(a[2]), "r"(a[3]), "r"(b0), "r"(b1));
}
// pack(a,b): lo = bf16(a), hi = bf16(b)   (one instruction)
__device__ __forceinline__ uint32_t packbf2(float a, float b) {
    uint32_t r;
    asm("cvt.rn.bf16x2.f32 %0, %1, %2;" : "=r"(r) : "f"(b), "f"(a));
    return r;
}
__device__ __forceinline__ uint32_t bfhi2(float a, float b) {
    return (uint32_t)__bfloat16_as_ushort(__float2bfloat16_rn(a))
         | ((uint32_t)__bfloat16_as_ushort(__float2bfloat16_rn(b)) << 16);
}
__device__ __forceinline__ float bfres(float a) {
    return a - __bfloat162float(__float2bfloat16_rn(a));
}
__device__ __forceinline__ unsigned short bfbits(float a) {
    return __bfloat16_as_ushort(__float2bfloat16_rn(a));
}
__device__ __forceinline__ float fast_tanh(float x) {
    float e = __expf(2.0f * x);
    return 1.0f - 2.0f / (e + 1.0f);
}

// ---------------------------------------------------------------------------
// prep_xifrag: per-node xi bf16 hi/lo A-fragments via ldmatrix.
// ---------------------------------------------------------------------------
__global__ void prep_xifrag(const float* __restrict__ x)
{
    __shared__ unsigned short img[128 * 40];
    const int tid = threadIdx.x, wid = tid >> 5, lane = tid & 31;
    const int m = blockIdx.x * 128 + tid;
    float xi[16];
    #pragma unroll
    for (int i = 0; i < 4; i++) {
        float4 v = __ldg((const float4*)(x + (size_t)m * 80 + 64 + 4 * i));
        xi[4*i] = v.x; xi[4*i+1] = v.y; xi[4*i+2] = v.z; xi[4*i+3] = v.w;
    }
    #pragma unroll
    for (int i = 0; i < 16; i++) {
        img[tid * 40 + i]      = bfbits(xi[i]);
        img[tid * 40 + 16 + i] = bfbits(bfres(xi[i]));
    }
    __syncthreads();

    const int a_row  = lane & 15;
    const int a_koff = (lane >> 4) << 3;
    const int g = blockIdx.x * 4 + wid;
    #pragma unroll
    for (int hl = 0; hl < 2; hl++)
        #pragma unroll
        for (int mi = 0; mi < 2; mi++) {
            const uint32_t addr = smem_u32(img)
                + (uint32_t)((wid * 32 + mi * 16 + a_row) * 40 + hl * 16 + a_koff) * 2;
            uint32_t r[4];
            ldsm_x4(r, addr);
            g_XIf[g][hl][mi][lane] = make_uint4(r[0], r[1], r[2], r[3]);
        }
}

// ---------------------------------------------------------------------------
// prep_bfrag: B fragments via the SAME ldmatrix addressing tc_phase uses.
// ---------------------------------------------------------------------------
__global__ void prep_bfrag(const float* __restrict__ W1q, const float* __restrict__ b1q,
                           const float* __restrict__ W2q,
                           const float* __restrict__ W1p, const float* __restrict__ b1p,
                           const float* __restrict__ W2p)
{
    const int net = blockIdx.x;
    const float* W1 = net ? W1p : W1q;
    const float* b1 = net ? b1p : b1q;
    const float* W2 = net ? W2p : W2q;
    __shared__ unsigned short img[128 * SA];     // reused 3x
    const int tid = threadIdx.x, wid = tid >> 5, lane = tid & 31;
    const int b_nofs = (lane & 7) + ((lane >> 4) << 3);
    const int b_koff = ((lane >> 3) & 1) << 3;

    // ---- B1 image: rows n 0..127, cols k 0..127 (k<64 hi, k>=64 lo), stride SA
    for (int idx = tid; idx < 128 * 128; idx += 128) {
        const int n = idx >> 7, k = idx & 127;
        const float v = W1[(k & 63) * 128 + n];
        img[n * SA + k] = bfbits(k < 64 ? v : bfres(v));
    }
    __syncthreads();
    {
        const uint32_t base = smem_u32(img) + (uint32_t)((wid * 32 + b_nofs) * SA + b_koff) * 2;
        for (int f = 0; f < 8; f++) {
            const int kimg = (f < 4) ? f * 16 : 64 + (f - 4) * 16;
            uint32_t r[4];
            ldsm_x4(r, base + kimg * 2);
            g_B1f[net][wid][f][0][lane] = make_uint4(r[0], r[1], r[2], r[3]);
            ldsm_x4(r, base + kimg * 2 + 16 * SA * 2);
            g_B1f[net][wid][f][1][lane] = make_uint4(r[0], r[1], r[2], r[3]);
        }
    }
    __syncthreads();

    // ---- B2 image: rows n 0..31, cols k 0..255 (k<128 hi, else lo), stride 264
    for (int idx = tid; idx < 32 * 256; idx += 128) {
        const int n = idx >> 8, k = idx & 255;
        const float v = W2[(k & 127) * 32 + n];
        img[n * 264 + k] = bfbits(k < 128 ? v : bfres(v));
    }
    __syncthreads();
    {
        const int l = lane & 15;
        const uint32_t base = smem_u32(img)
            + (uint32_t)((wid * 8 + (l & 7)) * 264 + (((l >> 3) & 1) << 3)) * 2;
        for (int f = 0; f < 16; f++) {
            const int kimg = (f < 8) ? f * 16 : 128 + (f - 8) * 16;
            uint32_t r[2];
            ldsm_x2(r, base + kimg * 2);
            g_B2f[net][wid][f][lane] = make_uint2(r[0], r[1]);
        }
    }
    __syncthreads();

    // ---- X image: rows n 0..127, cols 0..15 WXhi, 16..31 WXlo, 32=b1_hi 33=b1_lo
    for (int idx = tid; idx < 128 * 48; idx += 128) {
        const int n = idx / 48, k = idx % 48;
        float v = 0.0f;
        if (k < 16)       v = W1[(64 + k) * 128 + n];
        else if (k < 32)  v = bfres(W1[(64 + k - 16) * 128 + n]);
        else if (k == 32) v = b1[n];
        else if (k == 33) v = bfres(b1[n]);
        img[n * 56 + k] = bfbits(v);
    }
    __syncthreads();
    {
        const uint32_t base = smem_u32(img) + (uint32_t)((wid * 32 + b_nofs) * 56 + b_koff) * 2;
        for (int f = 0; f < 3; f++) {
            uint32_t r[4];
            ldsm_x4(r, base + f * 16 * 2);
            g_BXf[net][wid][f][0][lane] = make_uint4(r[0], r[1], r[2], r[3]);
            ldsm_x4(r, base + f * 16 * 2 + 16 * 56 * 2);
            g_BXf[net][wid][f][1][lane] = make_uint4(r[0], r[1], r[2], r[3]);
        }
    }
}

// ---------------------------------------------------------------------------
// One integrator phase.  256 threads, 64 nodes/block, 4 blocks/SM.
// GEMM2 runs entirely from registers (C-fragment -> A-fragment identity);
// cross-warp k-reduction via a small f32 smem exchange.
// ---------------------------------------------------------------------------
__global__ __launch_bounds__(NTHR, 4)
void tc_phase(float* __restrict__ state, const float* __restrict__ tfinal,
              const float* __restrict__ b2, const int* __restrict__ nbrs,
              int net, int roff, int woff, float t_base, float dt_max)
{
    extern __shared__ unsigned char smx[];
    const uint32_t sbase = smem_u32(smx);
    const int tid = threadIdx.x;
    const int wid = tid >> 5;
    const int lane = tid & 31;
    const int mblk = blockIdx.x;
    const int m0 = mblk * TMN;

    // ---- build A1 [64 x 128]: cols 0..63 = x_hi (self|nbr), 64..127 = x_lo ----
    {
        const int r = tid >> 2, part = tid & 3;   // part 0/1: self halves; 2/3: nbr halves
        const int m = m0 + r;
        float z[16];
        if (part < 2) {
            const float* p = state + (size_t)m * 80 + roff + part * 16;
            #pragma unroll
            for (int i = 0; i < 4; i++) {
                float4 v = ((const float4*)p)[i];
                z[4*i] = v.x; z[4*i+1] = v.y; z[4*i+2] = v.z; z[4*i+3] = v.w;
            }
        } else {
            const int b = m >> 12, n = m & (NN - 1);
            const int4 nb = *(const int4*)(nbrs + n * 4);
            const int nbase = b << 12;
            const int off = roff + (part - 2) * 16;
            const float* p0 = state + (size_t)(nbase + nb.x) * 80 + off;
            const float* p1 = state + (size_t)(nbase + nb.y) * 80 + off;
            const float* p2 = state + (size_t)(nbase + nb.z) * 80 + off;
            const float* p3 = state + (size_t)(nbase + nb.w) * 80 + off;
            #pragma unroll
            for (int i = 0; i < 4; i++) {
                float4 a0 = ((const float4*)p0)[i], a1 = ((const float4*)p1)[i];
                float4 a2 = ((const float4*)p2)[i], a3 = ((const float4*)p3)[i];
                z[4*i]   = 0.25f * ((a0.x + a1.x) + (a2.x + a3.x));
                z[4*i+1] = 0.25f * ((a0.y + a1.y) + (a2.y + a3.y));
                z[4*i+2] = 0.25f * ((a0.z + a1.z) + (a2.z + a3.z));
                z[4*i+3] = 0.25f * ((a0.w + a1.w) + (a2.w + a3.w));
            }
        }
        uint32_t hh[8], ll[8];
        #pragma unroll
        for (int i = 0; i < 8; i++) {
            const float x0 = z[2*i], x1 = z[2*i+1];
            const uint32_t u = packbf2(x0, x1);
            hh[i] = u;
            const float r0 = x0 - __uint_as_float(u << 16);
            const float r1 = x1 - __uint_as_float(u & 0xFFFF0000u);
            ll[i] = packbf2(r0, r1);
        }
        const int c0 = part * 16;
        *(uint4*)(smx + SM_A1 + (r * SA + c0) * 2)          = make_uint4(hh[0],hh[1],hh[2],hh[3]);
        *(uint4*)(smx + SM_A1 + (r * SA + c0 + 8) * 2)      = make_uint4(hh[4],hh[5],hh[6],hh[7]);
        *(uint4*)(smx + SM_A1 + (r * SA + 64 + c0) * 2)     = make_uint4(ll[0],ll[1],ll[2],ll[3]);
        *(uint4*)(smx + SM_A1 + (r * SA + 64 + c0 + 8) * 2) = make_uint4(ll[4],ll[5],ll[6],ll[7]);
    }

    const int a_row  = lane & 15;
    const int a_koff = (lane >> 4) << 3;
    const int wmI = wid >> 2, wnI = wid & 3;
    const int wm = wmI * 32;

    // ---- xi + bias k-steps (global fragments only -> before the barrier) ----
    float acc[2][4][4];
    #pragma unroll
    for (int mi = 0; mi < 2; mi++)
        #pragma unroll
        for (int nj = 0; nj < 4; nj++)
            #pragma unroll
            for (int e = 0; e < 4; e++) acc[mi][nj][e] = 0.0f;

    {
        const int g = mblk * 2 + wmI;
        uint32_t aH[2][4], aL[2][4];
        #pragma unroll
        for (int mi = 0; mi < 2; mi++) {
            const uint4 vh = __ldg(&g_XIf[g][0][mi][lane]);
            aH[mi][0] = vh.x; aH[mi][1] = vh.y; aH[mi][2] = vh.z; aH[mi][3] = vh.w;
            const uint4 vl = __ldg(&g_XIf[g][1][mi][lane]);
            aL[mi][0] = vl.x; aL[mi][1] = vl.y; aL[mi][2] = vl.z; aL[mi][3] = vl.w;
        }
        {   // xiH @ WXhi ; xiL @ WXhi
            const uint4 b0 = __ldg(&g_BXf[net][wnI][0][0][lane]);
            const uint4 b1v = __ldg(&g_BXf[net][wnI][0][1][lane]);
            #pragma unroll
            for (int mi = 0; mi < 2; mi++) {
                mma16816(acc[mi][0], aH[mi], b0.x, b0.y);
                mma16816(acc[mi][1], aH[mi], b0.z, b0.w);
                mma16816(acc[mi][2], aH[mi], b1v.x, b1v.y);
                mma16816(acc[mi][3], aH[mi], b1v.z, b1v.w);
                mma16816(acc[mi][0], aL[mi], b0.x, b0.y);
                mma16816(acc[mi][1], aL[mi], b0.z, b0.w);
                mma16816(acc[mi][2], aL[mi], b1v.x, b1v.y);
                mma16816(acc[mi][3], aL[mi], b1v.z, b1v.w);
            }
        }
        {   // xiH @ WXlo
            const uint4 b0 = __ldg(&g_BXf[net][wnI][1][0][lane]);
            const uint4 b1v = __ldg(&g_BXf[net][wnI][1][1][lane]);
            #pragma unroll
            for (int mi = 0; mi < 2; mi++) {
                mma16816(acc[mi][0], aH[mi], b0.x, b0.y);
                mma16816(acc[mi][1], aH[mi], b0.z, b0.w);
                mma16816(acc[mi][2], aH[mi], b1v.x, b1v.y);
                mma16816(acc[mi][3], aH[mi], b1v.z, b1v.w);
            }
        }
        {   // bias: A cols 0,1 = 1.0 (inline)
            uint32_t aBias[4];
            const uint32_t one2 = ((lane & 3) == 0) ? 0x3F803F80u : 0u;
            aBias[0] = one2; aBias[1] = one2; aBias[2] = 0u; aBias[3] = 0u;
            const uint4 b0 = __ldg(&g_BXf[net][wnI][2][0][lane]);
            const uint4 b1v = __ldg(&g_BXf[net][wnI][2][1][lane]);
            #pragma unroll
            for (int mi = 0; mi < 2; mi++) {
                mma16816(acc[mi][0], aBias, b0.x, b0.y);
                mma16816(acc[mi][1], aBias, b0.z, b0.w);
                mma16816(acc[mi][2], aBias, b1v.x, b1v.y);
                mma16816(acc[mi][3], aBias, b1v.z, b1v.w);
            }
        }
    }
    __syncthreads();

    const uint32_t aB = sbase + SM_A1 + (uint32_t)((wm + a_row) * SA + a_koff) * 2;

    // ---- GEMM1: x_hi@W_hi + x_hi@W_lo, then x_lo@W_hi ----
    #pragma unroll
    for (int ks = 0; ks < 4; ks++) {
        uint32_t af[2][4];
        ldsm_x4(af[0], aB + ks * 32);
        ldsm_x4(af[1], aB + ks * 32 + 16 * SA * 2);
        {
            const uint4 b0 = __ldg(&g_B1f[net][wnI][ks][0][lane]);
            const uint4 b1v = __ldg(&g_B1f[net][wnI][ks][1][lane]);
            #pragma unroll
            for (int mi = 0; mi < 2; mi++) {
                mma16816(acc[mi][0], af[mi], b0.x, b0.y);
                mma16816(acc[mi][1], af[mi], b0.z, b0.w);
                mma16816(acc[mi][2], af[mi], b1v.x, b1v.y);
                mma16816(acc[mi][3], af[mi], b1v.z, b1v.w);
            }
        }
        {
            const uint4 b0 = __ldg(&g_B1f[net][wnI][4 + ks][0][lane]);
            const uint4 b1v = __ldg(&g_B1f[net][wnI][4 + ks][1][lane]);
            #pragma unroll
            for (int mi = 0; mi < 2; mi++) {
                mma16816(acc[mi][0], af[mi], b0.x, b0.y);
                mma16816(acc[mi][1], af[mi], b0.z, b0.w);
                mma16816(acc[mi][2], af[mi], b1v.x, b1v.y);
                mma16816(acc[mi][3], af[mi], b1v.z, b1v.w);
            }
        }
    }
    #pragma unroll
    for (int ks = 0; ks < 4; ks++) {
        uint32_t af[2][4];
        ldsm_x4(af[0], aB + (64 + ks * 16) * 2);
        ldsm_x4(af[1], aB + (64 + ks * 16) * 2 + 16 * SA * 2);
        const uint4 b0 = __ldg(&g_B1f[net][wnI][ks][0][lane]);
        const uint4 b1v = __ldg(&g_B1f[net][wnI][ks][1][lane]);
        #pragma unroll
        for (int mi = 0; mi < 2; mi++) {
            mma16816(acc[mi][0], af[mi], b0.x, b0.y);
            mma16816(acc[mi][1], af[mi], b0.z, b0.w);
            mma16816(acc[mi][2], af[mi], b1v.x, b1v.y);
            mma16816(acc[mi][3], af[mi], b1v.z, b1v.w);
        }
    }

    // ---- GEMM2 in registers: tanh(C1) tile IS the A-fragment (hi + lo split).
    //      Each warp covers k-slice [wn, wn+32); partials reduced via smem. ----
    #pragma unroll
    for (int mi = 0; mi < 2; mi++) {
        uint32_t aH[2][4], aL[2][4];
        #pragma unroll
        for (int j = 0; j < 2; j++) {
            float t[8];
            #pragma unroll
            for (int q = 0; q < 2; q++)
                #pragma unroll
                for (int e = 0; e < 4; e++)
                    t[q*4+e] = fast_tanh(acc[mi][2*j+q][e]);
            #pragma unroll
            for (int p = 0; p < 4; p++) {
                const float x0 = t[2*p], x1 = t[2*p+1];
                const uint32_t u = packbf2(x0, x1);
                aH[j][p] = u;
                const float r0 = x0 - __uint_as_float(u << 16);
                const float r1 = x1 - __uint_as_float(u & 0xFFFF0000u);
                aL[j][p] = packbf2(r0, r1);
            }
        }
        float c2[4][4];
        #pragma unroll
        for (int g = 0; g < 4; g++)
            #pragma unroll
            for (int e = 0; e < 4; e++) c2[g][e] = 0.0f;

        #pragma unroll
        for (int g = 0; g < 4; g++) {
            #pragma unroll
            for (int j = 0; j < 2; j++) {
                const int ksi = 2 * wnI + j;
                const uint2 bh = __ldg(&g_B2f[net][g][ksi][lane]);
                const uint2 bl = __ldg(&g_B2f[net][g][8 + ksi][lane]);
                mma16816(c2[g], aH[j], bh.x, bh.y);
                mma16816(c2[g], aL[j], bh.x, bh.y);
                mma16816(c2[g], aH[j], bl.x, bl.y);
            }
        }
        #pragma unroll
        for (int g = 0; g < 4; g++) {
            float4 v = make_float4(c2[g][0], c2[g][1], c2[g][2], c2[g][3]);
            *(float4*)(smx + SM_RED
                + (uint32_t)(((((wmI * 4 + wnI) * 2 + mi) * 4 + g) * 32 + lane) * 16)) = v;
        }
    }
    __syncthreads();

    // ---- reduce 4 k-slice partials (this warp takes n-quarter g = wnI) + epilogue ----
    {
        const float tf = __ldg(tfinal + (m0 >> 12));
        const float dt = fminf(fmaxf(tf - t_base, 0.0f), dt_max);
        const int wn2 = wnI * 8;
        const int c0 = wn2 + (lane & 3) * 2;
        const float b2v0 = __ldg(b2 + c0);
        const float b2v1 = __ldg(b2 + c0 + 1);
        #pragma unroll
        for (int mi = 0; mi < 2; mi++) {
            float4 s = make_float4(0.0f, 0.0f, 0.0f, 0.0f);
            #pragma unroll
            for (int w = 0; w < 4; w++) {
                const float4 v = *(const float4*)(smx + SM_RED
                    + (uint32_t)(((((wmI * 4 + w) * 2 + mi) * 4 + wnI) * 32 + lane) * 16));
                s.x += v.x; s.y += v.y; s.z += v.z; s.w += v.w;
            }
            const int r0 = m0 + wm + mi * 16 + (lane >> 2);
            float* p0 = state + (size_t)r0 * 80 + woff + c0;
            p0[0] = fmaf(dt, s.x + b2v0, p0[0]);
            p0[1] = fmaf(dt, s.y + b2v1, p0[1]);
            float* p1 = state + (size_t)(r0 + 8) * 80 + woff + c0;
            p1[0] = fmaf(dt, s.z + b2v0, p1[0]);
            p1[1] = fmaf(dt, s.w + b2v1, p1[1]);
        }
    }
}

// ---------------------------------------------------------------------------
extern "C" void kernel_launch(void* const* d_in, const int* in_sizes, int n_in,
                              void* d_out, int out_size)
{
    const float* x   = (const float*)d_in[0];
    const float* tfi = (const float*)d_in[1];
    const float* W1q = (const float*)d_in[2];
    const float* b1q = (const float*)d_in[3];
    const float* W2q = (const float*)d_in[4];
    const float* b2q = (const float*)d_in[5];
    const float* W1p = (const float*)d_in[6];
    const float* b1p = (const float*)d_in[7];
    const float* W2p = (const float*)d_in[8];
    const float* b2p = (const float*)d_in[9];
    const int*  nbrs = (const int*)d_in[10];
    float* out = (float*)d_out;

    cudaFuncSetAttribute(tc_phase, cudaFuncAttributeMaxDynamicSharedMemorySize, SM_TOTAL);

    cudaMemcpyAsync(out, x, (size_t)NODES * 80 * sizeof(float),
                    cudaMemcpyDeviceToDevice);
    prep_xifrag<<<NODES / 128, 128>>>(x);
    prep_bfrag<<<2, 128>>>(W1q, b1q, W2q, W1p, b1p, W2p);

    float tq = 0.0f, tp = 0.0f;
    for (int k = 0; k < N_STEPS; k++) {
        const float rho = (k == 0) ? 0.5f : 1.0f;
        // q-update: reads p (offset 32), writes q (offset 0)
        tc_phase<<<NBLK, NTHR, SM_TOTAL>>>(out, tfi, b2q, nbrs, 0, POFF, 0, tq, rho * DT_STEP);
        tq += rho * DT_STEP;
        // p-update: reads q (offset 0), writes p (offset 32)
        tc_phase<<<NBLK, NTHR, SM_TOTAL>>>(out, tfi, b2p, nbrs, 1, 0, POFF, tp, DT_STEP);
        tp += DT_STEP;
    }
}

// round 13
// speedup vs baseline: 1.0951x; 1.0951x over previous
#include <cuda_runtime.h>
#include <cuda_bf16.h>
#include <cstdint>

#define NN       4096
#define NODES    32768
#define DT_STEP  0.25f
#define N_STEPS  18
#define TMN      32                  // nodes (M) per block
#define NBLK     (NODES / TMN)       // 1024
#define NTHR     128
#define POFF     32                  // p-field offset within 80-float node record

#define SA       136                 // row stride (elems) = 272 B (conflict-free ldsm)
#define SM_A1    0                                 // A1: 32 x 136 x 2B = 8704
#define SM_HH    8704                              // h_hi: 32 x 136 x 2B
#define SM_HL    (8704 * 2)                        // h_lo: 32 x 136 x 2B
#define SM_TOTAL (8704 * 3)                        // 26112 B -> 8 blocks/SM

// B1 fragments: [net][wn/32][f(0..3 hi,4..7 lo)][half][lane] (ldmatrix x4 regs)
__device__ uint4 g_B1f[2][4][8][2][32];
// B2 fragments: [net][n-group(8 cols)][k-tile(0..7 hi, 8..15 lo)][lane] (ldmatrix x2 regs)
__device__ uint2 g_B2f[2][4][16][32];
// xi A-side fragments per 32-node group: [g][hi/lo][mi][lane]
__device__ uint4 g_XIf[NODES / 32][2][2][32];
// xi/bias B-side fragments: [net][wn/32][f: 0=WXhi 1=WXlo 2=bias][half][lane]
__device__ uint4 g_BXf[2][4][3][2][32];

// ---------------------------------------------------------------------------
__device__ __forceinline__ uint32_t smem_u32(const void* p) {
    uint32_t a;
    asm("{ .reg .u64 t; cvta.to.shared.u64 t, %1; cvt.u32.u64 %0, t; }" : "=r"(a) : "l"(p));
    return a;
}
__device__ __forceinline__ void ldsm_x4(uint32_t (&r)[4], uint32_t addr) {
    asm volatile("ldmatrix.sync.aligned.m8n8.x4.shared.b16 {%0,%1,%2,%3}, [%4];"
        : "=r"(r[0]), "=r"(r[1]), "=r"(r[2]), "=r"(r[3]) : "r"(addr));
}
__device__ __forceinline__ void ldsm_x2(uint32_t (&r)[2], uint32_t addr) {
    asm volatile("ldmatrix.sync.aligned.m8n8.x2.shared.b16 {%0,%1}, [%2];"
        : "=r"(r[0]), "=r"(r[1]) : "r"(addr));
}
__device__ __forceinline__ void mma16816(float (&c)[4], const uint32_t (&a)[4],
                                         uint32_t b0, uint32_t b1) {
    asm volatile("mma.sync.aligned.m16n8k16.row.col.f32.bf16.bf16.f32 "
        "{%0,%1,%2,%3}, {%4,%5,%6,%7}, {%8,%9}, {%0,%1,%2,%3};"
        : "+f"(c[0]), "+f"(c[1]), "+f"(c[2]), "+f"(c[3])
        : "r"(a[0]), "r"(a[1]), "r"(a[2]), "r"(a[3]), "r"(b0), "r"(b1));
}
// pack(a,b): lo = bf16(a), hi = bf16(b)   (one instruction)
__device__ __forceinline__ uint32_t packbf2(float a, float b) {
    uint32_t r;
    asm("cvt.rn.bf16x2.f32 %0, %1, %2;" : "=r"(r) : "f"(b), "f"(a));
    return r;
}
__device__ __forceinline__ float bfres(float a) {
    return a - __bfloat162float(__float2bfloat16_rn(a));
}
__device__ __forceinline__ unsigned short bfbits(float a) {
    return __bfloat16_as_ushort(__float2bfloat16_rn(a));
}
__device__ __forceinline__ float fast_tanh(float x) {
    float e = __expf(2.0f * x);
    return 1.0f - 2.0f / (e + 1.0f);
}

// ---------------------------------------------------------------------------
// prep_xifrag: per-node xi bf16 hi/lo A-fragments via ldmatrix.
// ---------------------------------------------------------------------------
__global__ void prep_xifrag(const float* __restrict__ x)
{
    __shared__ unsigned short img[128 * 40];
    const int tid = threadIdx.x, wid = tid >> 5, lane = tid & 31;
    const int m = blockIdx.x * 128 + tid;
    float xi[16];
    #pragma unroll
    for (int i = 0; i < 4; i++) {
        float4 v = __ldg((const float4*)(x + (size_t)m * 80 + 64 + 4 * i));
        xi[4*i] = v.x; xi[4*i+1] = v.y; xi[4*i+2] = v.z; xi[4*i+3] = v.w;
    }
    #pragma unroll
    for (int i = 0; i < 16; i++) {
        img[tid * 40 + i]      = bfbits(xi[i]);
        img[tid * 40 + 16 + i] = bfbits(bfres(xi[i]));
    }
    __syncthreads();

    const int a_row  = lane & 15;
    const int a_koff = (lane >> 4) << 3;
    const int g = blockIdx.x * 4 + wid;
    #pragma unroll
    for (int hl = 0; hl < 2; hl++)
        #pragma unroll
        for (int mi = 0; mi < 2; mi++) {
            const uint32_t addr = smem_u32(img)
                + (uint32_t)((wid * 32 + mi * 16 + a_row) * 40 + hl * 16 + a_koff) * 2;
            uint32_t r[4];
            ldsm_x4(r, addr);
            g_XIf[g][hl][mi][lane] = make_uint4(r[0], r[1], r[2], r[3]);
        }
}

// ---------------------------------------------------------------------------
// prep_bfrag: B fragments via the SAME ldmatrix addressing tc_phase uses.
// ---------------------------------------------------------------------------
__global__ void prep_bfrag(const float* __restrict__ W1q, const float* __restrict__ b1q,
                           const float* __restrict__ W2q,
                           const float* __restrict__ W1p, const float* __restrict__ b1p,
                           const float* __restrict__ W2p)
{
    const int net = blockIdx.x;
    const float* W1 = net ? W1p : W1q;
    const float* b1 = net ? b1p : b1q;
    const float* W2 = net ? W2p : W2q;
    __shared__ unsigned short img[128 * SA];     // reused 3x
    const int tid = threadIdx.x, wid = tid >> 5, lane = tid & 31;
    const int b_nofs = (lane & 7) + ((lane >> 4) << 3);
    const int b_koff = ((lane >> 3) & 1) << 3;

    // ---- B1 image: rows n 0..127, cols k 0..127 (k<64 hi, k>=64 lo), stride SA
    for (int idx = tid; idx < 128 * 128; idx += 128) {
        const int n = idx >> 7, k = idx & 127;
        const float v = W1[(k & 63) * 128 + n];
        img[n * SA + k] = bfbits(k < 64 ? v : bfres(v));
    }
    __syncthreads();
    {
        const uint32_t base = smem_u32(img) + (uint32_t)((wid * 32 + b_nofs) * SA + b_koff) * 2;
        for (int f = 0; f < 8; f++) {
            const int kimg = (f < 4) ? f * 16 : 64 + (f - 4) * 16;
            uint32_t r[4];
            ldsm_x4(r, base + kimg * 2);
            g_B1f[net][wid][f][0][lane] = make_uint4(r[0], r[1], r[2], r[3]);
            ldsm_x4(r, base + kimg * 2 + 16 * SA * 2);
            g_B1f[net][wid][f][1][lane] = make_uint4(r[0], r[1], r[2], r[3]);
        }
    }
    __syncthreads();

    // ---- B2 image: rows n 0..31, cols k 0..255 (k<128 hi, else lo), stride 264
    for (int idx = tid; idx < 32 * 256; idx += 128) {
        const int n = idx >> 8, k = idx & 255;
        const float v = W2[(k & 127) * 32 + n];
        img[n * 264 + k] = bfbits(k < 128 ? v : bfres(v));
    }
    __syncthreads();
    {
        const int l = lane & 15;
        const uint32_t base = smem_u32(img)
            + (uint32_t)((wid * 8 + (l & 7)) * 264 + (((l >> 3) & 1) << 3)) * 2;
        for (int f = 0; f < 16; f++) {
            const int kimg = (f < 8) ? f * 16 : 128 + (f - 8) * 16;
            uint32_t r[2];
            ldsm_x2(r, base + kimg * 2);
            g_B2f[net][wid][f][lane] = make_uint2(r[0], r[1]);
        }
    }
    __syncthreads();

    // ---- X image: rows n 0..127, cols 0..15 WXhi, 16..31 WXlo, 32=b1_hi 33=b1_lo
    for (int idx = tid; idx < 128 * 48; idx += 128) {
        const int n = idx / 48, k = idx % 48;
        float v = 0.0f;
        if (k < 16)       v = W1[(64 + k) * 128 + n];
        else if (k < 32)  v = bfres(W1[(64 + k - 16) * 128 + n]);
        else if (k == 32) v = b1[n];
        else if (k == 33) v = bfres(b1[n]);
        img[n * 56 + k] = bfbits(v);
    }
    __syncthreads();
    {
        const uint32_t base = smem_u32(img) + (uint32_t)((wid * 32 + b_nofs) * 56 + b_koff) * 2;
        for (int f = 0; f < 3; f++) {
            uint32_t r[4];
            ldsm_x4(r, base + f * 16 * 2);
            g_BXf[net][wid][f][0][lane] = make_uint4(r[0], r[1], r[2], r[3]);
            ldsm_x4(r, base + f * 16 * 2 + 16 * 56 * 2);
            g_BXf[net][wid][f][1][lane] = make_uint4(r[0], r[1], r[2], r[3]);
        }
    }
}

// ---------------------------------------------------------------------------
// One integrator phase.  128 threads, 32 nodes/block, 8 blocks/SM, 1 wave.
// Warp w handles n-slice [w*32, w*32+32) of GEMM1 and n-cols [w*8, w*8+8)
// of GEMM2 over the block's full 32-node m-tile.
// ---------------------------------------------------------------------------
__global__ __launch_bounds__(NTHR, 8)
void tc_phase(float* __restrict__ state, const float* __restrict__ tfinal,
              const float* __restrict__ b2, const int* __restrict__ nbrs,
              int net, int roff, int woff, float t_base, float dt_max)
{
    extern __shared__ unsigned char smx[];
    const uint32_t sbase = smem_u32(smx);
    const int tid = threadIdx.x;
    const int wid = tid >> 5;
    const int lane = tid & 31;
    const int mblk = blockIdx.x;
    const int m0 = mblk * TMN;

    // ---- build A1 [32 x 128]: cols 0..63 = x_hi (self|nbr), 64..127 = x_lo ----
    {
        const int r = tid >> 2, part = tid & 3;   // part 0/1: self halves; 2/3: nbr halves
        const int m = m0 + r;
        float z[16];
        if (part < 2) {
            const float* p = state + (size_t)m * 80 + roff + part * 16;
            #pragma unroll
            for (int i = 0; i < 4; i++) {
                float4 v = ((const float4*)p)[i];
                z[4*i] = v.x; z[4*i+1] = v.y; z[4*i+2] = v.z; z[4*i+3] = v.w;
            }
        } else {
            const int b = m >> 12, n = m & (NN - 1);
            const int4 nb = *(const int4*)(nbrs + n * 4);
            const int nbase = b << 12;
            const int off = roff + (part - 2) * 16;
            const float* p0 = state + (size_t)(nbase + nb.x) * 80 + off;
            const float* p1 = state + (size_t)(nbase + nb.y) * 80 + off;
            const float* p2 = state + (size_t)(nbase + nb.z) * 80 + off;
            const float* p3 = state + (size_t)(nbase + nb.w) * 80 + off;
            #pragma unroll
            for (int i = 0; i < 4; i++) {
                float4 a0 = ((const float4*)p0)[i], a1 = ((const float4*)p1)[i];
                float4 a2 = ((const float4*)p2)[i], a3 = ((const float4*)p3)[i];
                z[4*i]   = 0.25f * ((a0.x + a1.x) + (a2.x + a3.x));
                z[4*i+1] = 0.25f * ((a0.y + a1.y) + (a2.y + a3.y));
                z[4*i+2] = 0.25f * ((a0.z + a1.z) + (a2.z + a3.z));
                z[4*i+3] = 0.25f * ((a0.w + a1.w) + (a2.w + a3.w));
            }
        }
        uint32_t hh[8], ll[8];
        #pragma unroll
        for (int i = 0; i < 8; i++) {
            const float x0 = z[2*i], x1 = z[2*i+1];
            const uint32_t u = packbf2(x0, x1);
            hh[i] = u;
            const float r0 = x0 - __uint_as_float(u << 16);
            const float r1 = x1 - __uint_as_float(u & 0xFFFF0000u);
            ll[i] = packbf2(r0, r1);
        }
        const int c0 = part * 16;
        *(uint4*)(smx + SM_A1 + (r * SA + c0) * 2)          = make_uint4(hh[0],hh[1],hh[2],hh[3]);
        *(uint4*)(smx + SM_A1 + (r * SA + c0 + 8) * 2)      = make_uint4(hh[4],hh[5],hh[6],hh[7]);
        *(uint4*)(smx + SM_A1 + (r * SA + 64 + c0) * 2)     = make_uint4(ll[0],ll[1],ll[2],ll[3]);
        *(uint4*)(smx + SM_A1 + (r * SA + 64 + c0 + 8) * 2) = make_uint4(ll[4],ll[5],ll[6],ll[7]);
    }

    const int a_row  = lane & 15;
    const int a_koff = (lane >> 4) << 3;
    const int wnI = wid;                 // 4 warps -> 4 n-slices

    // ---- xi + bias k-steps (global fragments only -> before the barrier) ----
    float acc[2][4][4];
    #pragma unroll
    for (int mi = 0; mi < 2; mi++)
        #pragma unroll
        for (int nj = 0; nj < 4; nj++)
            #pragma unroll
            for (int e = 0; e < 4; e++) acc[mi][nj][e] = 0.0f;

    {
        const int g = mblk;              // one 32-node group per block
        uint32_t aH[2][4], aL[2][4];
        #pragma unroll
        for (int mi = 0; mi < 2; mi++) {
            const uint4 vh = __ldg(&g_XIf[g][0][mi][lane]);
            aH[mi][0] = vh.x; aH[mi][1] = vh.y; aH[mi][2] = vh.z; aH[mi][3] = vh.w;
            const uint4 vl = __ldg(&g_XIf[g][1][mi][lane]);
            aL[mi][0] = vl.x; aL[mi][1] = vl.y; aL[mi][2] = vl.z; aL[mi][3] = vl.w;
        }
        {   // xiH @ WXhi ; xiL @ WXhi
            const uint4 b0 = __ldg(&g_BXf[net][wnI][0][0][lane]);
            const uint4 b1v = __ldg(&g_BXf[net][wnI][0][1][lane]);
            #pragma unroll
            for (int mi = 0; mi < 2; mi++) {
                mma16816(acc[mi][0], aH[mi], b0.x, b0.y);
                mma16816(acc[mi][1], aH[mi], b0.z, b0.w);
                mma16816(acc[mi][2], aH[mi], b1v.x, b1v.y);
                mma16816(acc[mi][3], aH[mi], b1v.z, b1v.w);
                mma16816(acc[mi][0], aL[mi], b0.x, b0.y);
                mma16816(acc[mi][1], aL[mi], b0.z, b0.w);
                mma16816(acc[mi][2], aL[mi], b1v.x, b1v.y);
                mma16816(acc[mi][3], aL[mi], b1v.z, b1v.w);
            }
        }
        {   // xiH @ WXlo
            const uint4 b0 = __ldg(&g_BXf[net][wnI][1][0][lane]);
            const uint4 b1v = __ldg(&g_BXf[net][wnI][1][1][lane]);
            #pragma unroll
            for (int mi = 0; mi < 2; mi++) {
                mma16816(acc[mi][0], aH[mi], b0.x, b0.y);
                mma16816(acc[mi][1], aH[mi], b0.z, b0.w);
                mma16816(acc[mi][2], aH[mi], b1v.x, b1v.y);
                mma16816(acc[mi][3], aH[mi], b1v.z, b1v.w);
            }
        }
        {   // bias: A cols 0,1 = 1.0 (inline)
            uint32_t aBias[4];
            const uint32_t one2 = ((lane & 3) == 0) ? 0x3F803F80u : 0u;
            aBias[0] = one2; aBias[1] = one2; aBias[2] = 0u; aBias[3] = 0u;
            const uint4 b0 = __ldg(&g_BXf[net][wnI][2][0][lane]);
            const uint4 b1v = __ldg(&g_BXf[net][wnI][2][1][lane]);
            #pragma unroll
            for (int mi = 0; mi < 2; mi++) {
                mma16816(acc[mi][0], aBias, b0.x, b0.y);
                mma16816(acc[mi][1], aBias, b0.z, b0.w);
                mma16816(acc[mi][2], aBias, b1v.x, b1v.y);
                mma16816(acc[mi][3], aBias, b1v.z, b1v.w);
            }
        }
    }
    __syncthreads();

    const uint32_t aB = sbase + SM_A1 + (uint32_t)(a_row * SA + a_koff) * 2;

    // ---- GEMM1: x_hi@W_hi + x_hi@W_lo, then x_lo@W_hi ----
    #pragma unroll
    for (int ks = 0; ks < 4; ks++) {
        uint32_t af[2][4];
        ldsm_x4(af[0], aB + ks * 32);
        ldsm_x4(af[1], aB + ks * 32 + 16 * SA * 2);
        {
            const uint4 b0 = __ldg(&g_B1f[net][wnI][ks][0][lane]);
            const uint4 b1v = __ldg(&g_B1f[net][wnI][ks][1][lane]);
            #pragma unroll
            for (int mi = 0; mi < 2; mi++) {
                mma16816(acc[mi][0], af[mi], b0.x, b0.y);
                mma16816(acc[mi][1], af[mi], b0.z, b0.w);
                mma16816(acc[mi][2], af[mi], b1v.x, b1v.y);
                mma16816(acc[mi][3], af[mi], b1v.z, b1v.w);
            }
        }
        {
            const uint4 b0 = __ldg(&g_B1f[net][wnI][4 + ks][0][lane]);
            const uint4 b1v = __ldg(&g_B1f[net][wnI][4 + ks][1][lane]);
            #pragma unroll
            for (int mi = 0; mi < 2; mi++) {
                mma16816(acc[mi][0], af[mi], b0.x, b0.y);
                mma16816(acc[mi][1], af[mi], b0.z, b0.w);
                mma16816(acc[mi][2], af[mi], b1v.x, b1v.y);
                mma16816(acc[mi][3], af[mi], b1v.z, b1v.w);
            }
        }
    }
    #pragma unroll
    for (int ks = 0; ks < 4; ks++) {
        uint32_t af[2][4];
        ldsm_x4(af[0], aB + (64 + ks * 16) * 2);
        ldsm_x4(af[1], aB + (64 + ks * 16) * 2 + 16 * SA * 2);
        const uint4 b0 = __ldg(&g_B1f[net][wnI][ks][0][lane]);
        const uint4 b1v = __ldg(&g_B1f[net][wnI][ks][1][lane]);
        #pragma unroll
        for (int mi = 0; mi < 2; mi++) {
            mma16816(acc[mi][0], af[mi], b0.x, b0.y);
            mma16816(acc[mi][1], af[mi], b0.z, b0.w);
            mma16816(acc[mi][2], af[mi], b1v.x, b1v.y);
            mma16816(acc[mi][3], af[mi], b1v.z, b1v.w);
        }
    }

    // ---- tanh -> h_hi / h_lo (conflict-free STS) ----
    {
        const int rb = lane >> 2;
        const int cbs = wnI * 32 + (lane & 3) * 2;
        #pragma unroll
        for (int mi = 0; mi < 2; mi++) {
            #pragma unroll
            for (int nj = 0; nj < 4; nj++) {
                const int c = cbs + nj * 8;
                #pragma unroll
                for (int hh = 0; hh < 2; hh++) {
                    const int r = rb + mi * 16 + hh * 8;
                    const float t0 = fast_tanh(acc[mi][nj][hh * 2 + 0]);
                    const float t1 = fast_tanh(acc[mi][nj][hh * 2 + 1]);
                    const uint32_t uh = packbf2(t0, t1);
                    const float r0 = t0 - __uint_as_float(uh << 16);
                    const float r1 = t1 - __uint_as_float(uh & 0xFFFF0000u);
                    *(uint32_t*)(smx + SM_HH + (r * SA + c) * 2) = uh;
                    *(uint32_t*)(smx + SM_HL + (r * SA + c) * 2) = packbf2(r0, r1);
                }
            }
        }
    }
    __syncthreads();

    // ---- GEMM2: h_hi@W2_hi + h_hi@W2_lo + h_lo@W2_hi ----
    const int wn2 = wnI * 8;
    float acc2[2][4];
    #pragma unroll
    for (int mi = 0; mi < 2; mi++)
        #pragma unroll
        for (int e = 0; e < 4; e++) acc2[mi][e] = 0.0f;

    const uint32_t hHB = sbase + SM_HH + (uint32_t)(a_row * SA + a_koff) * 2;
    const uint32_t hLB = sbase + SM_HL + (uint32_t)(a_row * SA + a_koff) * 2;
    #pragma unroll
    for (int ks = 0; ks < 8; ks++) {
        uint32_t af[2][4];
        ldsm_x4(af[0], hHB + ks * 32);
        ldsm_x4(af[1], hHB + ks * 32 + 16 * SA * 2);
        const uint2 bh = __ldg(&g_B2f[net][wnI][ks][lane]);
        const uint2 bl = __ldg(&g_B2f[net][wnI][8 + ks][lane]);
        mma16816(acc2[0], af[0], bh.x, bh.y);
        mma16816(acc2[1], af[1], bh.x, bh.y);
        mma16816(acc2[0], af[0], bl.x, bl.y);
        mma16816(acc2[1], af[1], bl.x, bl.y);
    }
    #pragma unroll
    for (int ks = 0; ks < 8; ks++) {
        uint32_t af[2][4];
        ldsm_x4(af[0], hLB + ks * 32);
        ldsm_x4(af[1], hLB + ks * 32 + 16 * SA * 2);
        const uint2 bh = __ldg(&g_B2f[net][wnI][ks][lane]);
        mma16816(acc2[0], af[0], bh.x, bh.y);
        mma16816(acc2[1], af[1], bh.x, bh.y);
    }

    // ---- epilogue: state += dt * (C2 + b2) ----
    {
        const float tf = __ldg(tfinal + (m0 >> 12));
        const float dt = fminf(fmaxf(tf - t_base, 0.0f), dt_max);
        const int c0 = wn2 + (lane & 3) * 2;
        const float b2v0 = __ldg(b2 + c0);
        const float b2v1 = __ldg(b2 + c0 + 1);
        #pragma unroll
        for (int mi = 0; mi < 2; mi++) {
            const int r0 = m0 + mi * 16 + (lane >> 2);
            float* p0 = state + (size_t)r0 * 80 + woff + c0;
            p0[0] = fmaf(dt, acc2[mi][0] + b2v0, p0[0]);
            p0[1] = fmaf(dt, acc2[mi][1] + b2v1, p0[1]);
            float* p1 = state + (size_t)(r0 + 8) * 80 + woff + c0;
            p1[0] = fmaf(dt, acc2[mi][2] + b2v0, p1[0]);
            p1[1] = fmaf(dt, acc2[mi][3] + b2v1, p1[1]);
        }
    }
}

// ---------------------------------------------------------------------------
extern "C" void kernel_launch(void* const* d_in, const int* in_sizes, int n_in,
                              void* d_out, int out_size)
{
    const float* x   = (const float*)d_in[0];
    const float* tfi = (const float*)d_in[1];
    const float* W1q = (const float*)d_in[2];
    const float* b1q = (const float*)d_in[3];
    const float* W2q = (const float*)d_in[4];
    const float* b2q = (const float*)d_in[5];
    const float* W1p = (const float*)d_in[6];
    const float* b1p = (const float*)d_in[7];
    const float* W2p = (const float*)d_in[8];
    const float* b2p = (const float*)d_in[9];
    const int*  nbrs = (const int*)d_in[10];
    float* out = (float*)d_out;

    cudaFuncSetAttribute(tc_phase, cudaFuncAttributeMaxDynamicSharedMemorySize, SM_TOTAL);

    cudaMemcpyAsync(out, x, (size_t)NODES * 80 * sizeof(float),
                    cudaMemcpyDeviceToDevice);
    prep_xifrag<<<NODES / 128, 128>>>(x);
    prep_bfrag<<<2, 128>>>(W1q, b1q, W2q, W1p, b1p, W2p);

    float tq = 0.0f, tp = 0.0f;
    for (int k = 0; k < N_STEPS; k++) {
        const float rho = (k == 0) ? 0.5f : 1.0f;
        // q-update: reads p (offset 32), writes q (offset 0)
        tc_phase<<<NBLK, NTHR, SM_TOTAL>>>(out, tfi, b2q, nbrs, 0, POFF, 0, tq, rho * DT_STEP);
        tq += rho * DT_STEP;
        // p-update: reads q (offset 0), writes p (offset 32)
        tc_phase<<<NBLK, NTHR, SM_TOTAL>>>(out, tfi, b2p, nbrs, 1, 0, POFF, tp, DT_STEP);
        tp += DT_STEP;
    }
}

// round 16
// speedup vs baseline: 1.4840x; 1.3551x over previous
#include <cuda_runtime.h>
#include <cuda_bf16.h>
#include <cuda_fp16.h>
#include <cstdint>

#define NN       4096
#define NODES    32768
#define DT_STEP  0.25f
#define N_STEPS  18
#define TMN      32                  // nodes (M) per block
#define NBLK     (NODES / TMN)       // 1024
#define NTHR     128
#define POFF     32                  // p-field offset within 80-float node record

#define SA       136                 // row stride (elems) = 272 B (conflict-free ldsm)
#define SM_A1    0                                 // A1: 32 x 136 x 2B = 8704
#define SM_HH    8704                              // h (fp16): 32 x 136 x 2B
#define SM_TOTAL (8704 * 2)                        // 17408 B -> 8 blocks/SM (reg-bound)

// B1 fragments: [net][wn/32][f(0..3 hi,4..7 lo)][half][lane] (ldmatrix x4 regs, bf16)
__device__ uint4 g_B1f[2][4][8][2][32];
// B2 fragments: [net][n-group(8 cols)][k-tile 0..7][lane] (ldmatrix x2 regs, fp16)
__device__ uint2 g_B2f[2][4][8][32];
// xi A-side fragments per 32-node group: [g][hi/lo][mi][lane] (bf16)
__device__ uint4 g_XIf[NODES / 32][2][2][32];
// xi/bias B-side fragments: [net][wn/32][f: 0=WXhi 1=WXlo 2=bias][half][lane] (bf16)
__device__ uint4 g_BXf[2][4][3][2][32];

// ---------------------------------------------------------------------------
__device__ __forceinline__ uint32_t smem_u32(const void* p) {
    uint32_t a;
    asm("{ .reg .u64 t; cvta.to.shared.u64 t, %1; cvt.u32.u64 %0, t; }" : "=r"(a) : "l"(p));
    return a;
}
__device__ __forceinline__ void ldsm_x4(uint32_t (&r)[4], uint32_t addr) {
    asm volatile("ldmatrix.sync.aligned.m8n8.x4.shared.b16 {%0,%1,%2,%3}, [%4];"
        : "=r"(r[0]), "=r"(r[1]), "=r"(r[2]), "=r"(r[3]) : "r"(addr));
}
__device__ __forceinline__ void ldsm_x2(uint32_t (&r)[2], uint32_t addr) {
    asm volatile("ldmatrix.sync.aligned.m8n8.x2.shared.b16 {%0,%1}, [%2];"
        : "=r"(r[0]), "=r"(r[1]) : "r"(addr));
}
// bf16 MMA (GEMM1 / xi section)
__device__ __forceinline__ void mma16816(float (&c)[4], const uint32_t (&a)[4],
                                         uint32_t b0, uint32_t b1) {
    asm volatile("mma.sync.aligned.m16n8k16.row.col.f32.bf16.bf16.f32 "
        "{%0,%1,%2,%3}, {%4,%5,%6,%7}, {%8,%9}, {%0,%1,%2,%3};"
        : "+f"(c[0]), "+f"(c[1]), "+f"(c[2]), "+f"(c[3])
        : "r"(a[0]), "r"(a[1]), "r"(a[2]), "r"(a[3]), "r"(b0), "r"(b1));
}
// fp16 MMA (GEMM2)
__device__ __forceinline__ void mma16816h(float (&c)[4], const uint32_t (&a)[4],
                                          uint32_t b0, uint32_t b1) {
    asm volatile("mma.sync.aligned.m16n8k16.row.col.f32.f16.f16.f32 "
        "{%0,%1,%2,%3}, {%4,%5,%6,%7}, {%8,%9}, {%0,%1,%2,%3};"
        : "+f"(c[0]), "+f"(c[1]), "+f"(c[2]), "+f"(c[3])
        : "r"(a[0]), "r"(a[1]), "r"(a[2]), "r"(a[3]), "r"(b0), "r"(b1));
}
// pack(a,b): lo halfword = bf16(a), hi = bf16(b)  (one instruction)
__device__ __forceinline__ uint32_t packbf2(float a, float b) {
    uint32_t r;
    asm("cvt.rn.bf16x2.f32 %0, %1, %2;" : "=r"(r) : "f"(b), "f"(a));
    return r;
}
// pack(a,b) fp16: lo halfword = f16(a), hi = f16(b)
__device__ __forceinline__ uint32_t packhf2(float a, float b) {
    uint32_t r;
    asm("cvt.rn.f16x2.f32 %0, %1, %2;" : "=r"(r) : "f"(b), "f"(a));
    return r;
}
__device__ __forceinline__ float bfres(float a) {
    return a - __bfloat162float(__float2bfloat16_rn(a));
}
__device__ __forceinline__ unsigned short bfbits(float a) {
    return __bfloat16_as_ushort(__float2bfloat16_rn(a));
}
__device__ __forceinline__ unsigned short hfbits(float a) {
    return __half_as_ushort(__float2half_rn(a));
}
__device__ __forceinline__ float tanh_hw(float x) {
    float y;
    asm("tanh.approx.f32 %0, %1;" : "=f"(y) : "f"(x));
    return y;
}

// ---------------------------------------------------------------------------
// prep_xifrag: per-node xi bf16 hi/lo A-fragments via ldmatrix.
// ---------------------------------------------------------------------------
__global__ void prep_xifrag(const float* __restrict__ x)
{
    __shared__ unsigned short img[128 * 40];
    const int tid = threadIdx.x, wid = tid >> 5, lane = tid & 31;
    const int m = blockIdx.x * 128 + tid;
    float xi[16];
    #pragma unroll
    for (int i = 0; i < 4; i++) {
        float4 v = __ldg((const float4*)(x + (size_t)m * 80 + 64 + 4 * i));
        xi[4*i] = v.x; xi[4*i+1] = v.y; xi[4*i+2] = v.z; xi[4*i+3] = v.w;
    }
    #pragma unroll
    for (int i = 0; i < 16; i++) {
        img[tid * 40 + i]      = bfbits(xi[i]);
        img[tid * 40 + 16 + i] = bfbits(bfres(xi[i]));
    }
    __syncthreads();

    const int a_row  = lane & 15;
    const int a_koff = (lane >> 4) << 3;
    const int g = blockIdx.x * 4 + wid;
    #pragma unroll
    for (int hl = 0; hl < 2; hl++)
        #pragma unroll
        for (int mi = 0; mi < 2; mi++) {
            const uint32_t addr = smem_u32(img)
                + (uint32_t)((wid * 32 + mi * 16 + a_row) * 40 + hl * 16 + a_koff) * 2;
            uint32_t r[4];
            ldsm_x4(r, addr);
            g_XIf[g][hl][mi][lane] = make_uint4(r[0], r[1], r[2], r[3]);
        }
}

// ---------------------------------------------------------------------------
// prep_bfrag: B fragments via the SAME ldmatrix addressing tc_phase uses.
// ---------------------------------------------------------------------------
__global__ void prep_bfrag(const float* __restrict__ W1q, const float* __restrict__ b1q,
                           const float* __restrict__ W2q,
                           const float* __restrict__ W1p, const float* __restrict__ b1p,
                           const float* __restrict__ W2p)
{
    const int net = blockIdx.x;
    const float* W1 = net ? W1p : W1q;
    const float* b1 = net ? b1p : b1q;
    const float* W2 = net ? W2p : W2q;
    __shared__ unsigned short img[128 * SA];     // reused 3x
    const int tid = threadIdx.x, wid = tid >> 5, lane = tid & 31;
    const int b_nofs = (lane & 7) + ((lane >> 4) << 3);
    const int b_koff = ((lane >> 3) & 1) << 3;

    // ---- B1 image: rows n 0..127, cols k 0..127 (k<64 hi, k>=64 lo), stride SA, bf16
    for (int idx = tid; idx < 128 * 128; idx += 128) {
        const int n = idx >> 7, k = idx & 127;
        const float v = W1[(k & 63) * 128 + n];
        img[n * SA + k] = bfbits(k < 64 ? v : bfres(v));
    }
    __syncthreads();
    {
        const uint32_t base = smem_u32(img) + (uint32_t)((wid * 32 + b_nofs) * SA + b_koff) * 2;
        for (int f = 0; f < 8; f++) {
            const int kimg = (f < 4) ? f * 16 : 64 + (f - 4) * 16;
            uint32_t r[4];
            ldsm_x4(r, base + kimg * 2);
            g_B1f[net][wid][f][0][lane] = make_uint4(r[0], r[1], r[2], r[3]);
            ldsm_x4(r, base + kimg * 2 + 16 * SA * 2);
            g_B1f[net][wid][f][1][lane] = make_uint4(r[0], r[1], r[2], r[3]);
        }
    }
    __syncthreads();

    // ---- B2 image: rows n 0..31, cols k 0..127, stride SA, fp16 (single-pass)
    for (int idx = tid; idx < 32 * 128; idx += 128) {
        const int n = idx >> 7, k = idx & 127;
        img[n * SA + k] = hfbits(W2[k * 32 + n]);
    }
    __syncthreads();
    {
        const int l = lane & 15;
        const uint32_t base = smem_u32(img)
            + (uint32_t)((wid * 8 + (l & 7)) * SA + (((l >> 3) & 1) << 3)) * 2;
        for (int f = 0; f < 8; f++) {
            uint32_t r[2];
            ldsm_x2(r, base + f * 16 * 2);
            g_B2f[net][wid][f][lane] = make_uint2(r[0], r[1]);
        }
    }
    __syncthreads();

    // ---- X image: rows n 0..127, cols 0..15 WXhi, 16..31 WXlo, 32=b1_hi 33=b1_lo (bf16)
    for (int idx = tid; idx < 128 * 48; idx += 128) {
        const int n = idx / 48, k = idx % 48;
        float v = 0.0f;
        if (k < 16)       v = W1[(64 + k) * 128 + n];
        else if (k < 32)  v = bfres(W1[(64 + k - 16) * 128 + n]);
        else if (k == 32) v = b1[n];
        else if (k == 33) v = bfres(b1[n]);
        img[n * 56 + k] = bfbits(v);
    }
    __syncthreads();
    {
        const uint32_t base = smem_u32(img) + (uint32_t)((wid * 32 + b_nofs) * 56 + b_koff) * 2;
        for (int f = 0; f < 3; f++) {
            uint32_t r[4];
            ldsm_x4(r, base + f * 16 * 2);
            g_BXf[net][wid][f][0][lane] = make_uint4(r[0], r[1], r[2], r[3]);
            ldsm_x4(r, base + f * 16 * 2 + 16 * 56 * 2);
            g_BXf[net][wid][f][1][lane] = make_uint4(r[0], r[1], r[2], r[3]);
        }
    }
}

// ---------------------------------------------------------------------------
// One integrator phase.  128 threads, 32 nodes/block, 8 blocks/SM, 1 wave.
// GEMM1: 3-term bf16 compensation.  GEMM2: single-pass fp16.
// ---------------------------------------------------------------------------
__global__ __launch_bounds__(NTHR, 8)
void tc_phase(float* __restrict__ state, const float* __restrict__ tfinal,
              const float* __restrict__ b2, const int* __restrict__ nbrs,
              int net, int roff, int woff, float t_base, float dt_max)
{
    extern __shared__ unsigned char smx[];
    const uint32_t sbase = smem_u32(smx);
    const int tid = threadIdx.x;
    const int wid = tid >> 5;
    const int lane = tid & 31;
    const int mblk = blockIdx.x;
    const int m0 = mblk * TMN;

    // ---- build A1 [32 x 128]: cols 0..63 = x_hi (self|nbr), 64..127 = x_lo ----
    {
        const int r = tid >> 2, part = tid & 3;   // part 0/1: self halves; 2/3: nbr halves
        const int m = m0 + r;
        float z[16];
        if (part < 2) {
            const float* p = state + (size_t)m * 80 + roff + part * 16;
            #pragma unroll
            for (int i = 0; i < 4; i++) {
                float4 v = ((const float4*)p)[i];
                z[4*i] = v.x; z[4*i+1] = v.y; z[4*i+2] = v.z; z[4*i+3] = v.w;
            }
        } else {
            const int b = m >> 12, n = m & (NN - 1);
            const int4 nb = *(const int4*)(nbrs + n * 4);
            const int nbase = b << 12;
            const int off = roff + (part - 2) * 16;
            const float* p0 = state + (size_t)(nbase + nb.x) * 80 + off;
            const float* p1 = state + (size_t)(nbase + nb.y) * 80 + off;
            const float* p2 = state + (size_t)(nbase + nb.z) * 80 + off;
            const float* p3 = state + (size_t)(nbase + nb.w) * 80 + off;
            #pragma unroll
            for (int i = 0; i < 4; i++) {
                float4 a0 = ((const float4*)p0)[i], a1 = ((const float4*)p1)[i];
                float4 a2 = ((const float4*)p2)[i], a3 = ((const float4*)p3)[i];
                z[4*i]   = 0.25f * ((a0.x + a1.x) + (a2.x + a3.x));
                z[4*i+1] = 0.25f * ((a0.y + a1.y) + (a2.y + a3.y));
                z[4*i+2] = 0.25f * ((a0.z + a1.z) + (a2.z + a3.z));
                z[4*i+3] = 0.25f * ((a0.w + a1.w) + (a2.w + a3.w));
            }
        }
        uint32_t hh[8], ll[8];
        #pragma unroll
        for (int i = 0; i < 8; i++) {
            const float x0 = z[2*i], x1 = z[2*i+1];
            const uint32_t u = packbf2(x0, x1);
            hh[i] = u;
            const float r0 = x0 - __uint_as_float(u << 16);
            const float r1 = x1 - __uint_as_float(u & 0xFFFF0000u);
            ll[i] = packbf2(r0, r1);
        }
        const int c0 = part * 16;
        *(uint4*)(smx + SM_A1 + (r * SA + c0) * 2)          = make_uint4(hh[0],hh[1],hh[2],hh[3]);
        *(uint4*)(smx + SM_A1 + (r * SA + c0 + 8) * 2)      = make_uint4(hh[4],hh[5],hh[6],hh[7]);
        *(uint4*)(smx + SM_A1 + (r * SA + 64 + c0) * 2)     = make_uint4(ll[0],ll[1],ll[2],ll[3]);
        *(uint4*)(smx + SM_A1 + (r * SA + 64 + c0 + 8) * 2) = make_uint4(ll[4],ll[5],ll[6],ll[7]);
    }

    const int a_row  = lane & 15;
    const int a_koff = (lane >> 4) << 3;
    const int wnI = wid;                 // 4 warps -> 4 n-slices

    // ---- xi + bias k-steps (global fragments only -> before the barrier) ----
    float acc[2][4][4];
    #pragma unroll
    for (int mi = 0; mi < 2; mi++)
        #pragma unroll
        for (int nj = 0; nj < 4; nj++)
            #pragma unroll
            for (int e = 0; e < 4; e++) acc[mi][nj][e] = 0.0f;

    {
        const int g = mblk;              // one 32-node group per block
        uint32_t aH[2][4], aL[2][4];
        #pragma unroll
        for (int mi = 0; mi < 2; mi++) {
            const uint4 vh = __ldg(&g_XIf[g][0][mi][lane]);
            aH[mi][0] = vh.x; aH[mi][1] = vh.y; aH[mi][2] = vh.z; aH[mi][3] = vh.w;
            const uint4 vl = __ldg(&g_XIf[g][1][mi][lane]);
            aL[mi][0] = vl.x; aL[mi][1] = vl.y; aL[mi][2] = vl.z; aL[mi][3] = vl.w;
        }
        {   // xiH @ WXhi ; xiL @ WXhi
            const uint4 b0 = __ldg(&g_BXf[net][wnI][0][0][lane]);
            const uint4 b1v = __ldg(&g_BXf[net][wnI][0][1][lane]);
            #pragma unroll
            for (int mi = 0; mi < 2; mi++) {
                mma16816(acc[mi][0], aH[mi], b0.x, b0.y);
                mma16816(acc[mi][1], aH[mi], b0.z, b0.w);
                mma16816(acc[mi][2], aH[mi], b1v.x, b1v.y);
                mma16816(acc[mi][3], aH[mi], b1v.z, b1v.w);
                mma16816(acc[mi][0], aL[mi], b0.x, b0.y);
                mma16816(acc[mi][1], aL[mi], b0.z, b0.w);
                mma16816(acc[mi][2], aL[mi], b1v.x, b1v.y);
                mma16816(acc[mi][3], aL[mi], b1v.z, b1v.w);
            }
        }
        {   // xiH @ WXlo
            const uint4 b0 = __ldg(&g_BXf[net][wnI][1][0][lane]);
            const uint4 b1v = __ldg(&g_BXf[net][wnI][1][1][lane]);
            #pragma unroll
            for (int mi = 0; mi < 2; mi++) {
                mma16816(acc[mi][0], aH[mi], b0.x, b0.y);
                mma16816(acc[mi][1], aH[mi], b0.z, b0.w);
                mma16816(acc[mi][2], aH[mi], b1v.x, b1v.y);
                mma16816(acc[mi][3], aH[mi], b1v.z, b1v.w);
            }
        }
        {   // bias: A cols 0,1 = 1.0 (inline)
            uint32_t aBias[4];
            const uint32_t one2 = ((lane & 3) == 0) ? 0x3F803F80u : 0u;
            aBias[0] = one2; aBias[1] = one2; aBias[2] = 0u; aBias[3] = 0u;
            const uint4 b0 = __ldg(&g_BXf[net][wnI][2][0][lane]);
            const uint4 b1v = __ldg(&g_BXf[net][wnI][2][1][lane]);
            #pragma unroll
            for (int mi = 0; mi < 2; mi++) {
                mma16816(acc[mi][0], aBias, b0.x, b0.y);
                mma16816(acc[mi][1], aBias, b0.z, b0.w);
                mma16816(acc[mi][2], aBias, b1v.x, b1v.y);
                mma16816(acc[mi][3], aBias, b1v.z, b1v.w);
            }
        }
    }
    __syncthreads();

    const uint32_t aB = sbase + SM_A1 + (uint32_t)(a_row * SA + a_koff) * 2;

    // ---- GEMM1: x_hi@W_hi + x_hi@W_lo, then x_lo@W_hi ----
    #pragma unroll
    for (int ks = 0; ks < 4; ks++) {
        uint32_t af[2][4];
        ldsm_x4(af[0], aB + ks * 32);
        ldsm_x4(af[1], aB + ks * 32 + 16 * SA * 2);
        {
            const uint4 b0 = __ldg(&g_B1f[net][wnI][ks][0][lane]);
            const uint4 b1v = __ldg(&g_B1f[net][wnI][ks][1][lane]);
            #pragma unroll
            for (int mi = 0; mi < 2; mi++) {
                mma16816(acc[mi][0], af[mi], b0.x, b0.y);
                mma16816(acc[mi][1], af[mi], b0.z, b0.w);
                mma16816(acc[mi][2], af[mi], b1v.x, b1v.y);
                mma16816(acc[mi][3], af[mi], b1v.z, b1v.w);
            }
        }
        {
            const uint4 b0 = __ldg(&g_B1f[net][wnI][4 + ks][0][lane]);
            const uint4 b1v = __ldg(&g_B1f[net][wnI][4 + ks][1][lane]);
            #pragma unroll
            for (int mi = 0; mi < 2; mi++) {
                mma16816(acc[mi][0], af[mi], b0.x, b0.y);
                mma16816(acc[mi][1], af[mi], b0.z, b0.w);
                mma16816(acc[mi][2], af[mi], b1v.x, b1v.y);
                mma16816(acc[mi][3], af[mi], b1v.z, b1v.w);
            }
        }
    }
    #pragma unroll
    for (int ks = 0; ks < 4; ks++) {
        uint32_t af[2][4];
        ldsm_x4(af[0], aB + (64 + ks * 16) * 2);
        ldsm_x4(af[1], aB + (64 + ks * 16) * 2 + 16 * SA * 2);
        const uint4 b0 = __ldg(&g_B1f[net][wnI][ks][0][lane]);
        const uint4 b1v = __ldg(&g_B1f[net][wnI][ks][1][lane]);
        #pragma unroll
        for (int mi = 0; mi < 2; mi++) {
            mma16816(acc[mi][0], af[mi], b0.x, b0.y);
            mma16816(acc[mi][1], af[mi], b0.z, b0.w);
            mma16816(acc[mi][2], af[mi], b1v.x, b1v.y);
            mma16816(acc[mi][3], af[mi], b1v.z, b1v.w);
        }
    }

    // ---- tanh (HW approx) -> h (fp16, conflict-free STS) ----
    {
        const int rb = lane >> 2;
        const int cbs = wnI * 32 + (lane & 3) * 2;
        #pragma unroll
        for (int mi = 0; mi < 2; mi++) {
            #pragma unroll
            for (int nj = 0; nj < 4; nj++) {
                const int c = cbs + nj * 8;
                #pragma unroll
                for (int hh = 0; hh < 2; hh++) {
                    const int r = rb + mi * 16 + hh * 8;
                    const float t0 = tanh_hw(acc[mi][nj][hh * 2 + 0]);
                    const float t1 = tanh_hw(acc[mi][nj][hh * 2 + 1]);
                    *(uint32_t*)(smx + SM_HH + (r * SA + c) * 2) = packhf2(t0, t1);
                }
            }
        }
    }
    __syncthreads();

    // ---- GEMM2 (fp16 single-pass): h @ W2 ----
    const int wn2 = wnI * 8;
    float acc2[2][4];
    #pragma unroll
    for (int mi = 0; mi < 2; mi++)
        #pragma unroll
        for (int e = 0; e < 4; e++) acc2[mi][e] = 0.0f;

    const uint32_t hHB = sbase + SM_HH + (uint32_t)(a_row * SA + a_koff) * 2;
    #pragma unroll
    for (int ks = 0; ks < 8; ks++) {
        uint32_t af[2][4];
        ldsm_x4(af[0], hHB + ks * 32);
        ldsm_x4(af[1], hHB + ks * 32 + 16 * SA * 2);
        const uint2 bh = __ldg(&g_B2f[net][wnI][ks][lane]);
        mma16816h(acc2[0], af[0], bh.x, bh.y);
        mma16816h(acc2[1], af[1], bh.x, bh.y);
    }

    // ---- epilogue: state += dt * (C2 + b2), float2-vectorized ----
    {
        const float tf = __ldg(tfinal + (m0 >> 12));
        const float dt = fminf(fmaxf(tf - t_base, 0.0f), dt_max);
        const int c0 = wn2 + (lane & 3) * 2;
        const float b2v0 = __ldg(b2 + c0);
        const float b2v1 = __ldg(b2 + c0 + 1);
        #pragma unroll
        for (int mi = 0; mi < 2; mi++) {
            const int r0 = m0 + mi * 16 + (lane >> 2);
            float2* p0 = (float2*)(state + (size_t)r0 * 80 + woff + c0);
            float2 v0 = *p0;
            v0.x = fmaf(dt, acc2[mi][0] + b2v0, v0.x);
            v0.y = fmaf(dt, acc2[mi][1] + b2v1, v0.y);
            *p0 = v0;
            float2* p1 = (float2*)(state + (size_t)(r0 + 8) * 80 + woff + c0);
            float2 v1 = *p1;
            v1.x = fmaf(dt, acc2[mi][2] + b2v0, v1.x);
            v1.y = fmaf(dt, acc2[mi][3] + b2v1, v1.y);
            *p1 = v1;
        }
    }
}

// ---------------------------------------------------------------------------
extern "C" void kernel_launch(void* const* d_in, const int* in_sizes, int n_in,
                              void* d_out, int out_size)
{
    const float* x   = (const float*)d_in[0];
    const float* tfi = (const float*)d_in[1];
    const float* W1q = (const float*)d_in[2];
    const float* b1q = (const float*)d_in[3];
    const float* W2q = (const float*)d_in[4];
    const float* b2q = (const float*)d_in[5];
    const float* W1p = (const float*)d_in[6];
    const float* b1p = (const float*)d_in[7];
    const float* W2p = (const float*)d_in[8];
    const float* b2p = (const float*)d_in[9];
    const int*  nbrs = (const int*)d_in[10];
    float* out = (float*)d_out;

    cudaFuncSetAttribute(tc_phase, cudaFuncAttributeMaxDynamicSharedMemorySize, SM_TOTAL);

    cudaMemcpyAsync(out, x, (size_t)NODES * 80 * sizeof(float),
                    cudaMemcpyDeviceToDevice);
    prep_xifrag<<<NODES / 128, 128>>>(x);
    prep_bfrag<<<2, 128>>>(W1q, b1q, W2q, W1p, b1p, W2p);

    float tq = 0.0f, tp = 0.0f;
    for (int k = 0; k < N_STEPS; k++) {
        const float rho = (k == 0) ? 0.5f : 1.0f;
        // q-update: reads p (offset 32), writes q (offset 0)
        tc_phase<<<NBLK, NTHR, SM_TOTAL>>>(out, tfi, b2q, nbrs, 0, POFF, 0, tq, rho * DT_STEP);
        tq += rho * DT_STEP;
        // p-update: reads q (offset 0), writes p (offset 32)
        tc_phase<<<NBLK, NTHR, SM_TOTAL>>>(out, tfi, b2p, nbrs, 1, 0, POFF, tp, DT_STEP);
        tp += DT_STEP;
    }
}